// round 5
// baseline (speedup 1.0000x reference)
#include <cuda_runtime.h>
#include <math.h>
#include <float.h>

// GaussianQuantRegularizer2 — fused codebook argmax + KL mean, single kernel.
// R5: 296 blocks (exactly 2/SM on 148 SMs) with balanced contiguous row-pair
// partition (kills the 2-vs-1-block wave imbalance), finalize fused via
// atomic last-block reduction (saves a launch; makes ncu -s 5 hit gqr_main).
//
// Identities: zhat == prior[idx] (STE cancels), kl_loss == mean(kl2)
// (ge+eq+le==1), argmax score == 16-dim dot f=[iv-1, mu*iv] . g_k=[-s^2/2, s].

#define THREADS 256
#define NPAIRS  512            // 1024 codes as 512 f32x2 code-pairs
#define NB      296            // 148 SMs * 2 blocks/SM
#define MAXBLK  512

__device__ float g_partials[MAXBLK];
__device__ unsigned int g_done = 0;

static __device__ __forceinline__ unsigned long long pack2f(float lo, float hi) {
    unsigned long long r;
    asm("mov.b64 %0, {%1, %2};" : "=l"(r) : "f"(lo), "f"(hi));
    return r;
}
static __device__ __forceinline__ void unpack2f(unsigned long long v, float &lo, float &hi) {
    asm("mov.b64 {%0, %1}, %2;" : "=f"(lo), "=f"(hi) : "l"(v));
}
static __device__ __forceinline__ unsigned long long ffma2(unsigned long long a,
                                                           unsigned long long b,
                                                           unsigned long long c) {
    unsigned long long d;
    asm("fma.rn.f32x2 %0, %1, %2, %3;" : "=l"(d) : "l"(a), "l"(b), "l"(c));
    return d;
}
static __device__ __forceinline__ unsigned long long fmul2(unsigned long long a,
                                                           unsigned long long b) {
    unsigned long long d;
    asm("mul.rn.f32x2 %0, %1, %2;" : "=l"(d) : "l"(a), "l"(b));
    return d;
}
static __device__ __forceinline__ unsigned long long fadd2(unsigned long long a,
                                                           unsigned long long b) {
    unsigned long long d;
    asm("add.rn.f32x2 %0, %1, %2;" : "=l"(d) : "l"(a), "l"(b));
    return d;
}

__global__ __launch_bounds__(THREADS, 2)
void gqr_main(const float* __restrict__ z, const float* __restrict__ prior,
              float* __restrict__ out, int nrows, long long idx_off,
              long long kl_off, float scale, int nblocks)
{
    // Codebook: [pair p][jj] -> ulonglong2 {(gA_t0,gB_t0),(gA_t1,gB_t1)},
    // t = 2jj, 2jj+1 over 16 features; A = code 2p, B = code 2p+1.
    extern __shared__ ulonglong2 cb[];   // 512*8 entries = 64 KB

    for (int e = threadIdx.x; e < NPAIRS * 8; e += THREADS) {
        int p  = e >> 3, jj = e & 7;
        int k0 = p * 2, k1 = k0 + 1;
        int t0 = jj * 2, t1 = t0 + 1;
        float a0, b0, a1, b1;
        if (t0 < 8) {   // quadratic features: -0.5 * s^2
            float x  = prior[k0 * 8 + t0]; a0 = -0.5f * x  * x;
            float y  = prior[k1 * 8 + t0]; b0 = -0.5f * y  * y;
            float x1 = prior[k0 * 8 + t1]; a1 = -0.5f * x1 * x1;
            float y1 = prior[k1 * 8 + t1]; b1 = -0.5f * y1 * y1;
        } else {        // linear features: s
            a0 = prior[k0 * 8 + t0 - 8]; b0 = prior[k1 * 8 + t0 - 8];
            a1 = prior[k0 * 8 + t1 - 8]; b1 = prior[k1 * 8 + t1 - 8];
        }
        ulonglong2 q; q.x = pack2f(a0, b0); q.y = pack2f(a1, b1);
        cb[e] = q;
    }
    __syncthreads();

    // Balanced contiguous partition of row-PAIRS across blocks.
    int npr   = nrows >> 1;
    int base  = npr / nblocks;
    int rem   = npr - base * nblocks;
    int blk   = blockIdx.x;
    int start = blk * base + min(blk, rem);
    int cnt   = base + (blk < rem ? 1 : 0);

    float klacc = 0.0f;

    for (int rr = threadIdx.x; rr < cnt; rr += THREADS) {
        int n0 = (start + rr) << 1;
        int bb = n0 >> 12;          // H*W = 4096
        int hw = n0 & 4095;         // even -> rows n0, n0+1 share bb
        const float* zp = z + ((size_t)bb << 16) + hw;

        unsigned long long fp[2][16];
        #pragma unroll
        for (int d = 0; d < 8; d++) {
            float2 mu2 = *(const float2*)(zp + ((size_t)d << 12));
            float2 lv2 = *(const float2*)(zp + ((size_t)(8 + d) << 12));
            #pragma unroll
            for (int r = 0; r < 2; r++) {
                float mu = r ? mu2.y : mu2.x;
                float lv = r ? lv2.y : lv2.x;
                lv = fminf(fmaxf(lv, -30.0f), 20.0f);
                float var = expf(lv);
                float iv  = 1.0f / var;
                fp[r][d]     = pack2f(iv - 1.0f, iv - 1.0f);
                float fl  = mu * iv;
                fp[r][8 + d] = pack2f(fl, fl);
                klacc += mu * mu + var - 1.0f - lv;
            }
        }

        // even/odd running max per row; strict '>' keeps first-max per half
        float bestE[2] = { -FLT_MAX, -FLT_MAX };
        float bestO[2] = { -FLT_MAX, -FLT_MAX };
        int   pE[2] = { 0, 0 }, pO[2] = { 0, 0 };

        const ulonglong2* cp = cb;
        #pragma unroll 2
        for (int p = 0; p < NPAIRS; p++) {
            ulonglong2 q[8];
            #pragma unroll
            for (int jj = 0; jj < 8; jj++) q[jj] = cp[jj];
            cp += 8;
            #pragma unroll
            for (int r = 0; r < 2; r++) {
                unsigned long long a0 = fmul2(fp[r][0], q[0].x);
                unsigned long long a1 = fmul2(fp[r][1], q[0].y);
                #pragma unroll
                for (int jj = 1; jj < 8; jj++) {
                    a0 = ffma2(fp[r][2 * jj],     q[jj].x, a0);
                    a1 = ffma2(fp[r][2 * jj + 1], q[jj].y, a1);
                }
                float s0, s1;
                unpack2f(fadd2(a0, a1), s0, s1);
                if (s0 > bestE[r]) { bestE[r] = s0; pE[r] = p; }
                if (s1 > bestO[r]) { bestO[r] = s1; pO[r] = p; }
            }
        }

        int idx[2];
        #pragma unroll
        for (int r = 0; r < 2; r++) {
            int ie = 2 * pE[r], io = 2 * pO[r] + 1;
            if (bestO[r] > bestE[r])      idx[r] = io;
            else if (bestO[r] < bestE[r]) idx[r] = ie;
            else                          idx[r] = min(ie, io);  // first-max tie
        }

        const float* pvA = prior + (size_t)idx[0] * 8;
        const float* pvB = prior + (size_t)idx[1] * 8;
        #pragma unroll
        for (int d = 0; d < 8; d++) {
            float2 o; o.x = pvA[d]; o.y = pvB[d];
            *(float2*)(out + (((size_t)(bb * 8 + d)) << 12) + hw) = o;
        }
        out[idx_off + n0]     = (float)idx[0];
        out[idx_off + n0 + 1] = (float)idx[1];
    }

    // deterministic block-level KL partial
    #pragma unroll
    for (int o = 16; o > 0; o >>= 1)
        klacc += __shfl_down_sync(0xFFFFFFFFu, klacc, o);
    __shared__ float red[THREADS / 32];
    __shared__ int last_flag;
    if ((threadIdx.x & 31) == 0) red[threadIdx.x >> 5] = klacc;
    __syncthreads();
    if (threadIdx.x == 0) {
        float s = 0.0f;
        #pragma unroll
        for (int i = 0; i < THREADS / 32; i++) s += red[i];
        g_partials[blockIdx.x] = s;
        __threadfence();
        unsigned int old = atomicAdd(&g_done, 1u);
        last_flag = (old == (unsigned int)(nblocks - 1)) ? 1 : 0;
    }
    __syncthreads();

    // last block fuses the finalize: sums partials, writes kl, resets counter
    if (last_flag) {
        __threadfence();
        float s = 0.0f;
        for (int i = threadIdx.x; i < nblocks; i += THREADS) s += g_partials[i];
        #pragma unroll
        for (int o = 16; o > 0; o >>= 1)
            s += __shfl_down_sync(0xFFFFFFFFu, s, o);
        if ((threadIdx.x & 31) == 0) red[threadIdx.x >> 5] = s;
        __syncthreads();
        if (threadIdx.x == 0) {
            float t = 0.0f;
            #pragma unroll
            for (int i = 0; i < THREADS / 32; i++) t += red[i];
            out[kl_off] = t * scale;
            g_done = 0;                 // reset for next graph replay
            __threadfence();
        }
    }
}

extern "C" void kernel_launch(void* const* d_in, const int* in_sizes, int n_in,
                              void* d_out, int out_size)
{
    const float* z     = (const float*)d_in[0];
    // d_in[1] (noise) is provably unused by the forward values.
    const float* prior = (const float*)d_in[2];
    float* out = (float*)d_out;

    int nrows = in_sizes[0] / 16;                       // 131072
    long long idx_off = (long long)out_size - (long long)nrows;
    if (idx_off < 1) idx_off = 1;
    long long kl_off  = idx_off - 1;

    int nblocks = NB;                                    // 296 = 148 SMs * 2
    float scale = (1.4426f * 0.5f) / (float)nrows;

    (void)cudaFuncSetAttribute(gqr_main,
                               cudaFuncAttributeMaxDynamicSharedMemorySize, 65536);
    gqr_main<<<nblocks, THREADS, 65536>>>(z, prior, out, nrows, idx_off,
                                          kl_off, scale, nblocks);
}

// round 6
// speedup vs baseline: 1.1212x; 1.1212x over previous
#include <cuda_runtime.h>
#include <math.h>
#include <float.h>

// GaussianQuantRegularizer2 — fused codebook argmax + KL mean, single kernel.
// R6: back to exact-fit 256-block grid (R5 balance was a non-fix); attack the
// measured latency-boundedness (fma=48%, issue=44% at occ 20%) with an explicit
// double-buffered smem prefetch (LDS hides under prior pair's FFMA2 block) and
// fmaxf-based score updates that take FSETP->@P off the critical path.
//
// Identities: zhat == prior[idx] (STE cancels), kl_loss == mean(kl2)
// (ge+eq+le==1), argmax score == 16-dim dot f=[iv-1, mu*iv] . g_k=[-s^2/2, s].

#define THREADS 256
#define NPAIRS  512            // 1024 codes as 512 f32x2 code-pairs
#define NB      256            // 65536 row-pairs / 256 threads
#define SMEM_ENT (NPAIRS * 8 + 8)   // +8 entries pad for tail prefetch over-read
#define SMEM_BYTES (SMEM_ENT * 16)  // 65664

__device__ float g_partials[NB];
__device__ unsigned int g_done = 0;

static __device__ __forceinline__ unsigned long long pack2f(float lo, float hi) {
    unsigned long long r;
    asm("mov.b64 %0, {%1, %2};" : "=l"(r) : "f"(lo), "f"(hi));
    return r;
}
static __device__ __forceinline__ void unpack2f(unsigned long long v, float &lo, float &hi) {
    asm("mov.b64 {%0, %1}, %2;" : "=f"(lo), "=f"(hi) : "l"(v));
}
static __device__ __forceinline__ unsigned long long ffma2(unsigned long long a,
                                                           unsigned long long b,
                                                           unsigned long long c) {
    unsigned long long d;
    asm("fma.rn.f32x2 %0, %1, %2, %3;" : "=l"(d) : "l"(a), "l"(b), "l"(c));
    return d;
}
static __device__ __forceinline__ unsigned long long fmul2(unsigned long long a,
                                                           unsigned long long b) {
    unsigned long long d;
    asm("mul.rn.f32x2 %0, %1, %2;" : "=l"(d) : "l"(a), "l"(b));
    return d;
}
static __device__ __forceinline__ unsigned long long fadd2(unsigned long long a,
                                                           unsigned long long b) {
    unsigned long long d;
    asm("add.rn.f32x2 %0, %1, %2;" : "=l"(d) : "l"(a), "l"(b));
    return d;
}

__global__ __launch_bounds__(THREADS, 2)
void gqr_main(const float* __restrict__ z, const float* __restrict__ prior,
              float* __restrict__ out, int nrows, long long idx_off,
              long long kl_off, float scale)
{
    // Codebook: [pair p][jj] -> ulonglong2 {(gA_t0,gB_t0),(gA_t1,gB_t1)},
    // t = 2jj, 2jj+1 over 16 features; A = code 2p, B = code 2p+1.
    extern __shared__ ulonglong2 cb[];   // 512*8 + 8 pad entries

    for (int e = threadIdx.x; e < NPAIRS * 8; e += THREADS) {
        int p  = e >> 3, jj = e & 7;
        int k0 = p * 2, k1 = k0 + 1;
        int t0 = jj * 2, t1 = t0 + 1;
        float a0, b0, a1, b1;
        if (t0 < 8) {   // quadratic features: -0.5 * s^2
            float x  = prior[k0 * 8 + t0]; a0 = -0.5f * x  * x;
            float y  = prior[k1 * 8 + t0]; b0 = -0.5f * y  * y;
            float x1 = prior[k0 * 8 + t1]; a1 = -0.5f * x1 * x1;
            float y1 = prior[k1 * 8 + t1]; b1 = -0.5f * y1 * y1;
        } else {        // linear features: s
            a0 = prior[k0 * 8 + t0 - 8]; b0 = prior[k1 * 8 + t0 - 8];
            a1 = prior[k0 * 8 + t1 - 8]; b1 = prior[k1 * 8 + t1 - 8];
        }
        ulonglong2 q; q.x = pack2f(a0, b0); q.y = pack2f(a1, b1);
        cb[e] = q;
    }
    // zero the prefetch pad (read but never used for results)
    if (threadIdx.x < 8) {
        ulonglong2 zq; zq.x = 0ULL; zq.y = 0ULL;
        cb[NPAIRS * 8 + threadIdx.x] = zq;
    }
    __syncthreads();

    int t = blockIdx.x * THREADS + threadIdx.x;   // one row-PAIR per thread
    int npr = nrows >> 1;
    float klacc = 0.0f;

    if (t < npr) {
        int n0 = t << 1;
        int bb = n0 >> 12;          // H*W = 4096
        int hw = n0 & 4095;         // even -> rows n0, n0+1 share bb
        const float* zp = z + ((size_t)bb << 16) + hw;

        unsigned long long fp[2][16];
        #pragma unroll
        for (int d = 0; d < 8; d++) {
            float2 mu2 = *(const float2*)(zp + ((size_t)d << 12));
            float2 lv2 = *(const float2*)(zp + ((size_t)(8 + d) << 12));
            #pragma unroll
            for (int r = 0; r < 2; r++) {
                float mu = r ? mu2.y : mu2.x;
                float lv = r ? lv2.y : lv2.x;
                lv = fminf(fmaxf(lv, -30.0f), 20.0f);
                float var = expf(lv);
                float iv  = 1.0f / var;
                fp[r][d]     = pack2f(iv - 1.0f, iv - 1.0f);
                float fl  = mu * iv;
                fp[r][8 + d] = pack2f(fl, fl);
                klacc += mu * mu + var - 1.0f - lv;
            }
        }

        float bestE[2] = { -FLT_MAX, -FLT_MAX };
        float bestO[2] = { -FLT_MAX, -FLT_MAX };
        int   pE[2] = { 0, 0 }, pO[2] = { 0, 0 };

        // double-buffered prefetch: q[buf] computes while q[buf^1] loads next
        ulonglong2 q[2][8];
        const ulonglong2* cp = cb;
        #pragma unroll
        for (int jj = 0; jj < 8; jj++) q[0][jj] = cp[jj];

        #define GQR_STEP(BUF, POFF)                                            \
        do {                                                                   \
            /* prefetch next pair into the other buffer (pad covers tail) */   \
            _Pragma("unroll")                                                  \
            for (int jj = 0; jj < 8; jj++)                                     \
                q[(BUF) ^ 1][jj] = cp[8 * ((POFF) + 1) + jj];                  \
            _Pragma("unroll")                                                  \
            for (int r = 0; r < 2; r++) {                                      \
                unsigned long long a0 = fmul2(fp[r][0], q[BUF][0].x);          \
                unsigned long long a1 = fmul2(fp[r][1], q[BUF][0].y);          \
                _Pragma("unroll")                                              \
                for (int jj = 1; jj < 8; jj++) {                               \
                    a0 = ffma2(fp[r][2 * jj],     q[BUF][jj].x, a0);           \
                    a1 = ffma2(fp[r][2 * jj + 1], q[BUF][jj].y, a1);           \
                }                                                              \
                float s0, s1;                                                  \
                unpack2f(fadd2(a0, a1), s0, s1);                               \
                bool g0 = s0 > bestE[r];                                       \
                bool g1 = s1 > bestO[r];                                       \
                bestE[r] = fmaxf(bestE[r], s0);                                \
                bestO[r] = fmaxf(bestO[r], s1);                                \
                pE[r] = g0 ? (p + (POFF)) : pE[r];                             \
                pO[r] = g1 ? (p + (POFF)) : pO[r];                             \
            }                                                                  \
        } while (0)

        for (int p = 0; p < NPAIRS; p += 2) {
            GQR_STEP(0, 0);
            GQR_STEP(1, 1);
            cp += 16;
        }
        #undef GQR_STEP

        int idx[2];
        #pragma unroll
        for (int r = 0; r < 2; r++) {
            int ie = 2 * pE[r], io = 2 * pO[r] + 1;
            if (bestO[r] > bestE[r])      idx[r] = io;
            else if (bestO[r] < bestE[r]) idx[r] = ie;
            else                          idx[r] = min(ie, io);  // first-max tie
        }

        const float* pvA = prior + (size_t)idx[0] * 8;
        const float* pvB = prior + (size_t)idx[1] * 8;
        #pragma unroll
        for (int d = 0; d < 8; d++) {
            float2 o; o.x = pvA[d]; o.y = pvB[d];
            *(float2*)(out + (((size_t)(bb * 8 + d)) << 12) + hw) = o;
        }
        out[idx_off + n0]     = (float)idx[0];
        out[idx_off + n0 + 1] = (float)idx[1];
    }

    // deterministic block-level KL partial
    #pragma unroll
    for (int o = 16; o > 0; o >>= 1)
        klacc += __shfl_down_sync(0xFFFFFFFFu, klacc, o);
    __shared__ float red[THREADS / 32];
    __shared__ int last_flag;
    if ((threadIdx.x & 31) == 0) red[threadIdx.x >> 5] = klacc;
    __syncthreads();
    if (threadIdx.x == 0) {
        float s = 0.0f;
        #pragma unroll
        for (int i = 0; i < THREADS / 32; i++) s += red[i];
        g_partials[blockIdx.x] = s;
        __threadfence();
        unsigned int old = atomicAdd(&g_done, 1u);
        last_flag = (old == (unsigned int)(NB - 1)) ? 1 : 0;
    }
    __syncthreads();

    // last block fuses the finalize: sums partials, writes kl, resets counter
    if (last_flag) {
        __threadfence();
        float s = 0.0f;
        for (int i = threadIdx.x; i < NB; i += THREADS) s += g_partials[i];
        #pragma unroll
        for (int o = 16; o > 0; o >>= 1)
            s += __shfl_down_sync(0xFFFFFFFFu, s, o);
        if ((threadIdx.x & 31) == 0) red[threadIdx.x >> 5] = s;
        __syncthreads();
        if (threadIdx.x == 0) {
            float tt = 0.0f;
            #pragma unroll
            for (int i = 0; i < THREADS / 32; i++) tt += red[i];
            out[kl_off] = tt * scale;
            g_done = 0;                 // reset for next graph replay
            __threadfence();
        }
    }
}

extern "C" void kernel_launch(void* const* d_in, const int* in_sizes, int n_in,
                              void* d_out, int out_size)
{
    const float* z     = (const float*)d_in[0];
    // d_in[1] (noise) is provably unused by the forward values.
    const float* prior = (const float*)d_in[2];
    float* out = (float*)d_out;

    int nrows = in_sizes[0] / 16;                       // 131072
    long long idx_off = (long long)out_size - (long long)nrows;
    if (idx_off < 1) idx_off = 1;
    long long kl_off  = idx_off - 1;

    float scale = (1.4426f * 0.5f) / (float)nrows;

    (void)cudaFuncSetAttribute(gqr_main,
                               cudaFuncAttributeMaxDynamicSharedMemorySize, SMEM_BYTES);
    gqr_main<<<NB, THREADS, SMEM_BYTES>>>(z, prior, out, nrows, idx_off,
                                          kl_off, scale);
}